// round 15
// baseline (speedup 1.0000x reference)
#include <cuda_runtime.h>
#include <cuda_fp16.h>
#include <mma.h>

using namespace nvcuda;

#define NN 100000
#define FF 128
#define HH 128
#define ZZ 64
#define EE 1600000
#define EPOS 200000
#define NCHUNK ((NN + 255) / 256)   // 391

// ---- scratch (static device globals) ----
__device__ __align__(16) int      g_cnt[NN];
__device__ __align__(16) int      g_bsum[512];
__device__ __align__(16) int      g_boff[512];
__device__ __align__(16) int      g_rowstart[NN + 1];
__device__ __align__(16) int      g_cursor[NN];
__device__ __align__(16) int      g_csr[EE];
__device__ __align__(16) float    g_dinv[NN];
__device__ __align__(16) unsigned g_hs1h[NN * 64];   // x@W1 (UNSCALED) as half2 (128 cols)
__device__ __align__(16) unsigned g_hh[NN * 64];     // relu output as half2 (128 cols)
__device__ __align__(16) unsigned g_hs2h[NN * 32];   // (h@W2)*dinv as half2 (64 cols)
__device__ __align__(16) unsigned g_lath[NN * 32];   // latent as half2 (64 cols)

// ---------------- histogram / dinv ----------------
__global__ void cnt_init_k() {
    int i = blockIdx.x * blockDim.x + threadIdx.x;
    if (i < NN) g_cnt[i] = 0;
}

__global__ void cnt_count_k(const int* __restrict__ ei) {
    int e = blockIdx.x * blockDim.x + threadIdx.x;
    if (e < EE) atomicAdd(&g_cnt[ei[EE + e]], 1);
}

__global__ void dinv_k() {
    int i = blockIdx.x * blockDim.x + threadIdx.x;
    if (i < NN) g_dinv[i] = rsqrtf((float)(g_cnt[i] + 1));
}

// ---------------- scan (3 small kernels) ----------------
__global__ void scan_bsum_k() {
    __shared__ int sh[256];
    int i = blockIdx.x * 256 + threadIdx.x;
    sh[threadIdx.x] = (i < NN) ? g_cnt[i] : 0;
    __syncthreads();
    for (int o = 128; o > 0; o >>= 1) {
        if (threadIdx.x < o) sh[threadIdx.x] += sh[threadIdx.x + o];
        __syncthreads();
    }
    if (threadIdx.x == 0) g_bsum[blockIdx.x] = sh[0];
}

__global__ void scan_boff_k() {
    __shared__ int sh[512];
    int t = threadIdx.x;
    int v = (t < NCHUNK) ? g_bsum[t] : 0;
    sh[t] = v;
    __syncthreads();
    for (int o = 1; o < 512; o <<= 1) {
        int add = (t >= o) ? sh[t - o] : 0;
        __syncthreads();
        sh[t] += add;
        __syncthreads();
    }
    g_boff[t] = sh[t] - v;
}

__global__ void scan_final_k() {
    __shared__ int sh[256];
    int t = threadIdx.x;
    int i = blockIdx.x * 256 + t;
    int v = (i < NN) ? g_cnt[i] : 0;
    sh[t] = v;
    __syncthreads();
    for (int o = 1; o < 256; o <<= 1) {
        int add = (t >= o) ? sh[t - o] : 0;
        __syncthreads();
        sh[t] += add;
        __syncthreads();
    }
    if (i < NN) {
        int rs = g_boff[blockIdx.x] + sh[t] - v;
        g_rowstart[i] = rs;
        g_cursor[i] = rs;
        if (i == NN - 1) g_rowstart[NN] = EE;
    }
}

__global__ void csr_fill_k(const int* __restrict__ ei) {
    int e = blockIdx.x * blockDim.x + threadIdx.x;
    if (e < EE) {
        int dst = ei[EE + e];
        int pos = atomicAdd(&g_cursor[dst], 1);
        g_csr[pos] = ei[e];
    }
}

// ---------------- wmma GEMM: out = half2( (X @ W) [* dinv[row] if SCALE] ) ----------------
// K fixed at 128. Block = 64 rows x NC cols, 256 threads = 8 warps.
template <int NC, bool XHALF, bool SCALE>
__device__ __forceinline__ void wgemm_body(const void* __restrict__ Xv,
                                           const float* __restrict__ W,
                                           unsigned* __restrict__ outh) {
    constexpr int XS = 136;                 // Xh row stride (halves), 16B-aligned rows
    constexpr int WS = NC + 8;              // Wh row stride (halves)
    constexpr int CS = NC + 4;              // Cs row stride (floats)
    constexpr int NH = NC / 2;              // half2 words per output row
    constexpr int NT = NC / 32;             // n-tiles per warp (4 or 2)
    constexpr int SM_A = 64 * XS * 2;       // 17408 B
    constexpr int SM_AB = SM_A + 64 * WS * 2;
    constexpr int SM_EPI = 64 * CS * 4;
    constexpr int SM_TOT = (SM_AB > SM_EPI) ? SM_AB : SM_EPI;
    __shared__ __align__(16) char sm[SM_TOT];
    half* Xh = (half*)sm;
    half* Wh = (half*)(sm + SM_A);
    float* Cs = (float*)sm;                  // aliases Xh/Wh post-compute

    const int tid = threadIdx.x;
    const int row0 = blockIdx.x * 64;
    const int wid = tid >> 5;
    const int rw = wid >> 1;                 // 0..3 row tile
    const int cw = wid & 1;                  // 0..1 col half

    // stage X tile [64][128] -> fp16 smem
    if (XHALF) {
        const unsigned* Xs = (const unsigned*)Xv;   // half2 words, 64/row
        for (int idx = tid; idx < 64 * 64; idx += 256) {
            int r = idx >> 6, c2 = idx & 63;
            int gr = row0 + r;
            unsigned v = (gr < NN) ? Xs[(long)gr * 64 + c2] : 0u;
            *(unsigned*)&Xh[r * XS + 2 * c2] = v;
        }
    } else {
        const float* Xf = (const float*)Xv;
        for (int idx = tid; idx < 64 * 64; idx += 256) {
            int r = idx >> 6, c2 = idx & 63;
            int gr = row0 + r;
            float2 v = (gr < NN) ? *(const float2*)&Xf[(long)gr * 128 + 2 * c2]
                                 : make_float2(0.f, 0.f);
            __half2 h = __float22half2_rn(v);
            *(unsigned*)&Xh[r * XS + 2 * c2] = *(unsigned*)&h;
        }
    }

    wmma::fragment<wmma::accumulator, 16, 16, 16, float> acc[NT];
#pragma unroll
    for (int t = 0; t < NT; t++) wmma::fill_fragment(acc[t], 0.0f);

    for (int kb = 0; kb < 128; kb += 64) {
        for (int idx = tid; idx < 64 * NH; idx += 256) {
            int kr = idx / NH, c2 = idx % NH;
            float2 v = *(const float2*)&W[(long)(kb + kr) * NC + 2 * c2];
            __half2 h = __float22half2_rn(v);
            *(unsigned*)&Wh[kr * WS + 2 * c2] = *(unsigned*)&h;
        }
        __syncthreads();
#pragma unroll
        for (int k0 = 0; k0 < 64; k0 += 16) {
            wmma::fragment<wmma::matrix_a, 16, 16, 16, half, wmma::row_major> af;
            wmma::load_matrix_sync(af, &Xh[(rw * 16) * XS + kb + k0], XS);
#pragma unroll
            for (int t = 0; t < NT; t++) {
                wmma::fragment<wmma::matrix_b, 16, 16, 16, half, wmma::row_major> bf;
                wmma::load_matrix_sync(bf, &Wh[k0 * WS + cw * NH + t * 16], WS);
                wmma::mma_sync(acc[t], af, bf, acc[t]);
            }
        }
        __syncthreads();
    }

    // epilogue: stage fp32, optional dinv scale, emit half2
#pragma unroll
    for (int t = 0; t < NT; t++)
        wmma::store_matrix_sync(&Cs[(rw * 16) * CS + cw * NH + t * 16], acc[t],
                                CS, wmma::mem_row_major);
    __syncthreads();
    for (int idx = tid; idx < 64 * NH; idx += 256) {
        int r = idx / NH, c2 = idx % NH;
        int gr = row0 + r;
        if (gr < NN) {
            float s = SCALE ? g_dinv[gr] : 1.0f;
            float2 v = make_float2(Cs[r * CS + 2 * c2] * s,
                                   Cs[r * CS + 2 * c2 + 1] * s);
            __half2 h = __float22half2_rn(v);
            outh[(long)gr * NH + c2] = *(unsigned*)&h;
        }
    }
}

__global__ void __launch_bounds__(256) gemm1_k(const float* __restrict__ x,
                                               const float* __restrict__ W1) {
    wgemm_body<HH, false, false>(x, W1, g_hs1h);   // UNSCALED: no dinv dependency
}
__global__ void __launch_bounds__(256) gemm2_k(const float* __restrict__ W2) {
    wgemm_body<ZZ, true, true>(g_hh, W2, g_hs2h);
}

// ---------------- gather1: fp16 rows, dinv[src] applied per row, fp32 accum ----------------
__device__ __forceinline__ void h2fma4(float4& acc, uint2 v, float d) {
    float2 lo = __half22float2(*(__half2*)&v.x);
    float2 hi = __half22float2(*(__half2*)&v.y);
    acc.x = fmaf(d, lo.x, acc.x);
    acc.y = fmaf(d, lo.y, acc.y);
    acc.z = fmaf(d, hi.x, acc.z);
    acc.w = fmaf(d, hi.y, acc.w);
}

__global__ void gather1_k(const float* __restrict__ b1) {
    int gt = blockIdx.x * blockDim.x + threadIdx.x;
    int n = gt >> 5;
    int lane = gt & 31;
    if (n >= NN) return;
    int s = g_rowstart[n];
    int e = g_rowstart[n + 1];
    float dn = g_dinv[n];

    float4 acc = make_float4(0.f, 0.f, 0.f, 0.f);
    h2fma4(acc, *(const uint2*)&g_hs1h[(long)n * 64 + lane * 2], dn);  // self-loop

    for (int base = s; base < e; base += 32) {
        int idx = base + lane;
        int myi = (idx < e) ? g_csr[idx] : 0;
        float myd = (idx < e) ? g_dinv[myi] : 0.0f;
        int cnt = min(32, e - base);
        int j = 0;
        for (; j + 8 <= cnt; j += 8) {
            int ss[8];
            float dd[8];
#pragma unroll
            for (int q = 0; q < 8; q++) {
                ss[q] = __shfl_sync(0xffffffffu, myi, j + q);
                dd[q] = __shfl_sync(0xffffffffu, myd, j + q);
            }
            uint2 vv[8];
#pragma unroll
            for (int q = 0; q < 8; q++)
                vv[q] = *(const uint2*)&g_hs1h[(long)ss[q] * 64 + lane * 2];
#pragma unroll
            for (int q = 0; q < 8; q++) h2fma4(acc, vv[q], dd[q]);
        }
        for (; j < cnt; j++) {
            int s0 = __shfl_sync(0xffffffffu, myi, j);
            float d0 = __shfl_sync(0xffffffffu, myd, j);
            h2fma4(acc, *(const uint2*)&g_hs1h[(long)s0 * 64 + lane * 2], d0);
        }
    }
    float4 bb = *(const float4*)&b1[lane * 4];
    float4 o;
    o.x = fmaxf(fmaf(dn, acc.x, bb.x), 0.0f);
    o.y = fmaxf(fmaf(dn, acc.y, bb.y), 0.0f);
    o.z = fmaxf(fmaf(dn, acc.z, bb.z), 0.0f);
    o.w = fmaxf(fmaf(dn, acc.w, bb.w), 0.0f);
    __half2 h0 = __float22half2_rn(make_float2(o.x, o.y));
    __half2 h1 = __float22half2_rn(make_float2(o.z, o.w));
    *(uint2*)&g_hh[(long)n * 64 + lane * 2] =
        make_uint2(*(unsigned*)&h0, *(unsigned*)&h1);
}

// ---------------- gather2: fp16 rows (64 cols), fp32 accumulation ----------------
__global__ void gather2_k(const float* __restrict__ b2) {
    int gt = blockIdx.x * blockDim.x + threadIdx.x;
    int n = gt >> 5;
    int lane = gt & 31;
    if (n >= NN) return;
    int s = g_rowstart[n];
    int e = g_rowstart[n + 1];

    float2 acc;
    {
        unsigned v = g_hs2h[(long)n * 32 + lane];  // self-loop (scaled)
        acc = __half22float2(*(__half2*)&v);
    }

    for (int base = s; base < e; base += 32) {
        int idx = base + lane;
        int myi = (idx < e) ? g_csr[idx] : 0;
        int cnt = min(32, e - base);
        int j = 0;
        for (; j + 8 <= cnt; j += 8) {
            int ss[8];
#pragma unroll
            for (int q = 0; q < 8; q++) ss[q] = __shfl_sync(0xffffffffu, myi, j + q);
            unsigned vv[8];
#pragma unroll
            for (int q = 0; q < 8; q++)
                vv[q] = g_hs2h[(long)ss[q] * 32 + lane];
#pragma unroll
            for (int q = 0; q < 8; q++) {
                float2 f = __half22float2(*(__half2*)&vv[q]);
                acc.x += f.x; acc.y += f.y;
            }
        }
        for (; j < cnt; j++) {
            int s0 = __shfl_sync(0xffffffffu, myi, j);
            unsigned v = g_hs2h[(long)s0 * 32 + lane];
            float2 f = __half22float2(*(__half2*)&v);
            acc.x += f.x; acc.y += f.y;
        }
    }
    float d = g_dinv[n];
    float2 bb = *(const float2*)&b2[lane * 2];
    float2 o;
    o.x = fmaf(d, acc.x, bb.x);
    o.y = fmaf(d, acc.y, bb.y);
    __half2 hv = __float22half2_rn(o);
    g_lath[(long)n * 32 + lane] = *(unsigned*)&hv;
}

// ---------------- decoder: fp16 latent ----------------
__global__ void decode_k(const int* __restrict__ pe,
                         const int* __restrict__ ne,
                         float* __restrict__ out) {
    int gt = blockIdx.x * blockDim.x + threadIdx.x;
    int w = gt >> 5;
    int lane = gt & 31;
    if (w >= 2 * EPOS) return;
    int a, b;
    if (w < EPOS) {
        a = pe[w];
        b = pe[EPOS + w];
    } else {
        int k = w - EPOS;
        a = ne[k];
        b = ne[EPOS + k];
    }
    unsigned ua = g_lath[(long)a * 32 + lane];
    unsigned ub = g_lath[(long)b * 32 + lane];
    float2 u = __half22float2(*(__half2*)&ua);
    float2 v = __half22float2(*(__half2*)&ub);
    float s = u.x * v.x + u.y * v.y;
#pragma unroll
    for (int o = 16; o > 0; o >>= 1) s += __shfl_xor_sync(0xffffffffu, s, o);
    if (lane == 0) out[w] = s;
}

// ---------------- launch: gemm1 at t=0, FULL CSR chain concurrent on sB ----------------
extern "C" void kernel_launch(void* const* d_in, const int* in_sizes, int n_in,
                              void* d_out, int out_size) {
    const float* x = (const float*)d_in[0];
    const float* W1 = (const float*)d_in[1];
    const float* b1 = (const float*)d_in[2];
    const float* W2 = (const float*)d_in[3];
    const float* b2 = (const float*)d_in[4];
    const int* ei = (const int*)d_in[5];
    const int* pe = (const int*)d_in[6];
    const int* ne = (const int*)d_in[7];
    float* out = (float*)d_out;

    static cudaStream_t sB = nullptr;
    static cudaEvent_t evF = nullptr, evJ = nullptr;
    if (sB == nullptr) {
        cudaStreamCreateWithFlags(&sB, cudaStreamNonBlocking);
        cudaEventCreateWithFlags(&evF, cudaEventDisableTiming);
        cudaEventCreateWithFlags(&evJ, cudaEventDisableTiming);
    }

    // fork immediately: whole histogram+dinv+scan+fill chain on sB;
    // gemm1 (no dinv dependency now) on stream 0 from t=0
    cudaEventRecord(evF, 0);
    cudaStreamWaitEvent(sB, evF, 0);

    cnt_init_k<<<(NN + 255) / 256, 256, 0, sB>>>();
    cnt_count_k<<<(EE + 255) / 256, 256, 0, sB>>>(ei);
    dinv_k<<<(NN + 255) / 256, 256, 0, sB>>>();
    scan_bsum_k<<<NCHUNK, 256, 0, sB>>>();
    scan_boff_k<<<1, 512, 0, sB>>>();
    scan_final_k<<<NCHUNK, 256, 0, sB>>>();
    csr_fill_k<<<(EE + 255) / 256, 256, 0, sB>>>(ei);
    cudaEventRecord(evJ, sB);

    gemm1_k<<<(NN + 63) / 64, 256>>>(x, W1);

    // join: gather1 needs csr + dinv + gemm1
    cudaStreamWaitEvent(0, evJ, 0);

    gather1_k<<<(NN * 32 + 255) / 256, 256>>>(b1);
    gemm2_k<<<(NN + 63) / 64, 256>>>(W2);
    gather2_k<<<(NN * 32 + 255) / 256, 256>>>(b2);
    decode_k<<<(2 * EPOS * 32 + 255) / 256, 256>>>(pe, ne, out);
}

// round 16
// speedup vs baseline: 1.0010x; 1.0010x over previous
#include <cuda_runtime.h>
#include <cuda_fp16.h>
#include <mma.h>

using namespace nvcuda;

#define NN 100000
#define FF 128
#define HH 128
#define ZZ 64
#define EE 1600000
#define EPOS 200000
#define NCHUNK ((NN + 255) / 256)   // 391
#define NSPLIT 50048                 // 64-aligned node split for chunk overlap

// ---- scratch (static device globals) ----
__device__ __align__(16) int      g_cnt[NN];
__device__ __align__(16) int      g_bsum[512];
__device__ __align__(16) int      g_boff[512];
__device__ __align__(16) int      g_rowstart[NN + 1];
__device__ __align__(16) int      g_cursor[NN];
__device__ __align__(16) int      g_csr[EE];
__device__ __align__(16) float    g_dinv[NN];
__device__ __align__(16) unsigned g_hs1h[NN * 64];   // (x@W1)*dinv as half2 (128 cols)
__device__ __align__(16) unsigned g_hh[NN * 64];     // relu output as half2 (128 cols)
__device__ __align__(16) unsigned g_hs2h[NN * 32];   // (h@W2)*dinv as half2 (64 cols)
__device__ __align__(16) unsigned g_lath[NN * 32];   // latent as half2 (64 cols)

// ---------------- histogram / dinv ----------------
__global__ void cnt_init_k() {
    int i = blockIdx.x * blockDim.x + threadIdx.x;
    if (i < NN) g_cnt[i] = 0;
}

__global__ void cnt_count_k(const int* __restrict__ ei) {
    int t = blockIdx.x * blockDim.x + threadIdx.x;
    if (t < EE / 4) {
        int4 d = ((const int4*)(ei + EE))[t];
        atomicAdd(&g_cnt[d.x], 1);
        atomicAdd(&g_cnt[d.y], 1);
        atomicAdd(&g_cnt[d.z], 1);
        atomicAdd(&g_cnt[d.w], 1);
    }
}

__global__ void dinv_k() {
    int i = blockIdx.x * blockDim.x + threadIdx.x;
    if (i < NN) g_dinv[i] = rsqrtf((float)(g_cnt[i] + 1));
}

// ---------------- scan (3 small kernels) ----------------
__global__ void scan_bsum_k() {
    __shared__ int sh[256];
    int i = blockIdx.x * 256 + threadIdx.x;
    sh[threadIdx.x] = (i < NN) ? g_cnt[i] : 0;
    __syncthreads();
    for (int o = 128; o > 0; o >>= 1) {
        if (threadIdx.x < o) sh[threadIdx.x] += sh[threadIdx.x + o];
        __syncthreads();
    }
    if (threadIdx.x == 0) g_bsum[blockIdx.x] = sh[0];
}

__global__ void scan_boff_k() {
    __shared__ int sh[512];
    int t = threadIdx.x;
    int v = (t < NCHUNK) ? g_bsum[t] : 0;
    sh[t] = v;
    __syncthreads();
    for (int o = 1; o < 512; o <<= 1) {
        int add = (t >= o) ? sh[t - o] : 0;
        __syncthreads();
        sh[t] += add;
        __syncthreads();
    }
    g_boff[t] = sh[t] - v;
}

__global__ void scan_final_k() {
    __shared__ int sh[256];
    int t = threadIdx.x;
    int i = blockIdx.x * 256 + t;
    int v = (i < NN) ? g_cnt[i] : 0;
    sh[t] = v;
    __syncthreads();
    for (int o = 1; o < 256; o <<= 1) {
        int add = (t >= o) ? sh[t - o] : 0;
        __syncthreads();
        sh[t] += add;
        __syncthreads();
    }
    if (i < NN) {
        int rs = g_boff[blockIdx.x] + sh[t] - v;
        g_rowstart[i] = rs;
        g_cursor[i] = rs;
        if (i == NN - 1) g_rowstart[NN] = EE;
    }
}

__global__ void csr_fill_k(const int* __restrict__ ei) {
    int t = blockIdx.x * blockDim.x + threadIdx.x;
    if (t < EE / 4) {
        int4 s = ((const int4*)ei)[t];
        int4 d = ((const int4*)(ei + EE))[t];
        int p0 = atomicAdd(&g_cursor[d.x], 1); g_csr[p0] = s.x;
        int p1 = atomicAdd(&g_cursor[d.y], 1); g_csr[p1] = s.y;
        int p2 = atomicAdd(&g_cursor[d.z], 1); g_csr[p2] = s.z;
        int p3 = atomicAdd(&g_cursor[d.w], 1); g_csr[p3] = s.w;
    }
}

// ---------------- wmma GEMM: out = half2( (X @ W) * dinv[row] ) ----------------
// K fixed at 128. Block = 64 rows x NC cols, 256 threads = 8 warps.
template <int NC, bool XHALF>
__device__ __forceinline__ void wgemm_body(const void* __restrict__ Xv,
                                           const float* __restrict__ W,
                                           unsigned* __restrict__ outh,
                                           int rowbase) {
    constexpr int XS = 136;
    constexpr int WS = NC + 8;
    constexpr int CS = NC + 4;
    constexpr int NH = NC / 2;
    constexpr int NT = NC / 32;
    constexpr int SM_A = 64 * XS * 2;
    constexpr int SM_AB = SM_A + 64 * WS * 2;
    constexpr int SM_EPI = 64 * CS * 4;
    constexpr int SM_TOT = (SM_AB > SM_EPI) ? SM_AB : SM_EPI;
    __shared__ __align__(16) char sm[SM_TOT];
    half* Xh = (half*)sm;
    half* Wh = (half*)(sm + SM_A);
    float* Cs = (float*)sm;

    const int tid = threadIdx.x;
    const int row0 = rowbase + blockIdx.x * 64;
    const int wid = tid >> 5;
    const int rw = wid >> 1;
    const int cw = wid & 1;

    if (XHALF) {
        const unsigned* Xs = (const unsigned*)Xv;
        for (int idx = tid; idx < 64 * 64; idx += 256) {
            int r = idx >> 6, c2 = idx & 63;
            int gr = row0 + r;
            unsigned v = (gr < NN) ? Xs[(long)gr * 64 + c2] : 0u;
            *(unsigned*)&Xh[r * XS + 2 * c2] = v;
        }
    } else {
        const float* Xf = (const float*)Xv;
        for (int idx = tid; idx < 64 * 64; idx += 256) {
            int r = idx >> 6, c2 = idx & 63;
            int gr = row0 + r;
            float2 v = (gr < NN) ? *(const float2*)&Xf[(long)gr * 128 + 2 * c2]
                                 : make_float2(0.f, 0.f);
            __half2 h = __float22half2_rn(v);
            *(unsigned*)&Xh[r * XS + 2 * c2] = *(unsigned*)&h;
        }
    }

    wmma::fragment<wmma::accumulator, 16, 16, 16, float> acc[NT];
#pragma unroll
    for (int t = 0; t < NT; t++) wmma::fill_fragment(acc[t], 0.0f);

    for (int kb = 0; kb < 128; kb += 64) {
        for (int idx = tid; idx < 64 * NH; idx += 256) {
            int kr = idx / NH, c2 = idx % NH;
            float2 v = *(const float2*)&W[(long)(kb + kr) * NC + 2 * c2];
            __half2 h = __float22half2_rn(v);
            *(unsigned*)&Wh[kr * WS + 2 * c2] = *(unsigned*)&h;
        }
        __syncthreads();
#pragma unroll
        for (int k0 = 0; k0 < 64; k0 += 16) {
            wmma::fragment<wmma::matrix_a, 16, 16, 16, half, wmma::row_major> af;
            wmma::load_matrix_sync(af, &Xh[(rw * 16) * XS + kb + k0], XS);
#pragma unroll
            for (int t = 0; t < NT; t++) {
                wmma::fragment<wmma::matrix_b, 16, 16, 16, half, wmma::row_major> bf;
                wmma::load_matrix_sync(bf, &Wh[k0 * WS + cw * NH + t * 16], WS);
                wmma::mma_sync(acc[t], af, bf, acc[t]);
            }
        }
        __syncthreads();
    }

#pragma unroll
    for (int t = 0; t < NT; t++)
        wmma::store_matrix_sync(&Cs[(rw * 16) * CS + cw * NH + t * 16], acc[t],
                                CS, wmma::mem_row_major);
    __syncthreads();
    for (int idx = tid; idx < 64 * NH; idx += 256) {
        int r = idx / NH, c2 = idx % NH;
        int gr = row0 + r;
        if (gr < NN) {
            float s = g_dinv[gr];
            float2 v = make_float2(Cs[r * CS + 2 * c2] * s,
                                   Cs[r * CS + 2 * c2 + 1] * s);
            __half2 h = __float22half2_rn(v);
            outh[(long)gr * NH + c2] = *(unsigned*)&h;
        }
    }
}

__global__ void __launch_bounds__(256) gemm1_k(const float* __restrict__ x,
                                               const float* __restrict__ W1) {
    wgemm_body<HH, false>(x, W1, g_hs1h, 0);
}
__global__ void __launch_bounds__(256) gemm2_k(const float* __restrict__ W2, int rowbase) {
    wgemm_body<ZZ, true>(g_hh, W2, g_hs2h, rowbase);
}

// ---------------- gather1: fp16 rows (128 cols), fp32 accumulation, node range ----------------
__device__ __forceinline__ void h2acc4(float4& acc, uint2 v) {
    float2 lo = __half22float2(*(__half2*)&v.x);
    float2 hi = __half22float2(*(__half2*)&v.y);
    acc.x += lo.x; acc.y += lo.y; acc.z += hi.x; acc.w += hi.y;
}

__global__ void gather1_k(const float* __restrict__ b1, int n0, int n1) {
    int gt = blockIdx.x * blockDim.x + threadIdx.x;
    int n = n0 + (gt >> 5);
    int lane = gt & 31;
    if (n >= n1) return;
    int s = g_rowstart[n];
    int e = g_rowstart[n + 1];

    float4 acc = make_float4(0.f, 0.f, 0.f, 0.f);
    h2acc4(acc, *(const uint2*)&g_hs1h[(long)n * 64 + lane * 2]);  // self-loop

    for (int base = s; base < e; base += 32) {
        int idx = base + lane;
        int myi = (idx < e) ? g_csr[idx] : 0;
        int cnt = min(32, e - base);
        int j = 0;
        for (; j + 8 <= cnt; j += 8) {
            int ss[8];
#pragma unroll
            for (int q = 0; q < 8; q++) ss[q] = __shfl_sync(0xffffffffu, myi, j + q);
            uint2 vv[8];
#pragma unroll
            for (int q = 0; q < 8; q++)
                vv[q] = *(const uint2*)&g_hs1h[(long)ss[q] * 64 + lane * 2];
#pragma unroll
            for (int q = 0; q < 8; q++) h2acc4(acc, vv[q]);
        }
        for (; j < cnt; j++) {
            int s0 = __shfl_sync(0xffffffffu, myi, j);
            h2acc4(acc, *(const uint2*)&g_hs1h[(long)s0 * 64 + lane * 2]);
        }
    }
    float d = g_dinv[n];
    float4 bb = *(const float4*)&b1[lane * 4];
    float4 o;
    o.x = fmaxf(fmaf(d, acc.x, bb.x), 0.0f);
    o.y = fmaxf(fmaf(d, acc.y, bb.y), 0.0f);
    o.z = fmaxf(fmaf(d, acc.z, bb.z), 0.0f);
    o.w = fmaxf(fmaf(d, acc.w, bb.w), 0.0f);
    __half2 h0 = __float22half2_rn(make_float2(o.x, o.y));
    __half2 h1 = __float22half2_rn(make_float2(o.z, o.w));
    *(uint2*)&g_hh[(long)n * 64 + lane * 2] =
        make_uint2(*(unsigned*)&h0, *(unsigned*)&h1);
}

// ---------------- gather2: fp16 rows (64 cols), fp32 accumulation ----------------
__global__ void gather2_k(const float* __restrict__ b2) {
    int gt = blockIdx.x * blockDim.x + threadIdx.x;
    int n = gt >> 5;
    int lane = gt & 31;
    if (n >= NN) return;
    int s = g_rowstart[n];
    int e = g_rowstart[n + 1];

    float2 acc;
    {
        unsigned v = g_hs2h[(long)n * 32 + lane];  // self-loop (scaled)
        acc = __half22float2(*(__half2*)&v);
    }

    for (int base = s; base < e; base += 32) {
        int idx = base + lane;
        int myi = (idx < e) ? g_csr[idx] : 0;
        int cnt = min(32, e - base);
        int j = 0;
        for (; j + 8 <= cnt; j += 8) {
            int ss[8];
#pragma unroll
            for (int q = 0; q < 8; q++) ss[q] = __shfl_sync(0xffffffffu, myi, j + q);
            unsigned vv[8];
#pragma unroll
            for (int q = 0; q < 8; q++)
                vv[q] = g_hs2h[(long)ss[q] * 32 + lane];
#pragma unroll
            for (int q = 0; q < 8; q++) {
                float2 f = __half22float2(*(__half2*)&vv[q]);
                acc.x += f.x; acc.y += f.y;
            }
        }
        for (; j < cnt; j++) {
            int s0 = __shfl_sync(0xffffffffu, myi, j);
            unsigned v = g_hs2h[(long)s0 * 32 + lane];
            float2 f = __half22float2(*(__half2*)&v);
            acc.x += f.x; acc.y += f.y;
        }
    }
    float d = g_dinv[n];
    float2 bb = *(const float2*)&b2[lane * 2];
    float2 o;
    o.x = fmaf(d, acc.x, bb.x);
    o.y = fmaf(d, acc.y, bb.y);
    __half2 hv = __float22half2_rn(o);
    g_lath[(long)n * 32 + lane] = *(unsigned*)&hv;
}

// ---------------- decoder: fp16 latent ----------------
__global__ void decode_k(const int* __restrict__ pe,
                         const int* __restrict__ ne,
                         float* __restrict__ out) {
    int gt = blockIdx.x * blockDim.x + threadIdx.x;
    int w = gt >> 5;
    int lane = gt & 31;
    if (w >= 2 * EPOS) return;
    int a, b;
    if (w < EPOS) {
        a = pe[w];
        b = pe[EPOS + w];
    } else {
        int k = w - EPOS;
        a = ne[k];
        b = ne[EPOS + k];
    }
    unsigned ua = g_lath[(long)a * 32 + lane];
    unsigned ub = g_lath[(long)b * 32 + lane];
    float2 u = __half22float2(*(__half2*)&ua);
    float2 v = __half22float2(*(__half2*)&ub);
    float s = u.x * v.x + u.y * v.y;
#pragma unroll
    for (int o = 16; o > 0; o >>= 1) s += __shfl_xor_sync(0xffffffffu, s, o);
    if (lane == 0) out[w] = s;
}

// ---------------- launch (R14 structure + chunked gather1/gemm2 overlap) ----------------
extern "C" void kernel_launch(void* const* d_in, const int* in_sizes, int n_in,
                              void* d_out, int out_size) {
    const float* x = (const float*)d_in[0];
    const float* W1 = (const float*)d_in[1];
    const float* b1 = (const float*)d_in[2];
    const float* W2 = (const float*)d_in[3];
    const float* b2 = (const float*)d_in[4];
    const int* ei = (const int*)d_in[5];
    const int* pe = (const int*)d_in[6];
    const int* ne = (const int*)d_in[7];
    float* out = (float*)d_out;

    static cudaStream_t sB = nullptr;
    static cudaEvent_t evF = nullptr, evJ = nullptr, evA = nullptr, evB = nullptr;
    if (sB == nullptr) {
        cudaStreamCreateWithFlags(&sB, cudaStreamNonBlocking);
        cudaEventCreateWithFlags(&evF, cudaEventDisableTiming);
        cudaEventCreateWithFlags(&evJ, cudaEventDisableTiming);
        cudaEventCreateWithFlags(&evA, cudaEventDisableTiming);
        cudaEventCreateWithFlags(&evB, cudaEventDisableTiming);
    }

    // serial prefix: degree histogram (both branches need it)
    cnt_init_k<<<(NN + 255) / 256, 256>>>();
    cnt_count_k<<<(EE / 4 + 255) / 256, 256>>>(ei);

    // fork: scan+fill on sB; dinv+gemm1 on stream 0
    cudaEventRecord(evF, 0);
    cudaStreamWaitEvent(sB, evF, 0);
    scan_bsum_k<<<NCHUNK, 256, 0, sB>>>();
    scan_boff_k<<<1, 512, 0, sB>>>();
    scan_final_k<<<NCHUNK, 256, 0, sB>>>();
    csr_fill_k<<<(EE / 4 + 255) / 256, 256, 0, sB>>>(ei);
    cudaEventRecord(evJ, sB);

    dinv_k<<<(NN + 255) / 256, 256>>>();
    gemm1_k<<<(NN + 63) / 64, 256>>>(x, W1);

    // join: gather1 needs csr + gemm1
    cudaStreamWaitEvent(0, evJ, 0);

    // chunked tail: gemm2(c0) on sB overlaps gather1(c1) on stream 0
    gather1_k<<<(NSPLIT * 32 + 255) / 256, 256>>>(b1, 0, NSPLIT);
    cudaEventRecord(evA, 0);
    cudaStreamWaitEvent(sB, evA, 0);
    gemm2_k<<<NSPLIT / 64, 256, 0, sB>>>(W2, 0);
    cudaEventRecord(evB, sB);

    gather1_k<<<((NN - NSPLIT) * 32 + 255) / 256, 256>>>(b1, NSPLIT, NN);
    gemm2_k<<<(NN - NSPLIT + 63) / 64, 256>>>(W2, NSPLIT);

    cudaStreamWaitEvent(0, evB, 0);
    gather2_k<<<(NN * 32 + 255) / 256, 256>>>(b2);
    decode_k<<<(2 * EPOS * 32 + 255) / 256, 256>>>(pe, ne, out);
}

// round 17
// speedup vs baseline: 1.0166x; 1.0156x over previous
#include <cuda_runtime.h>
#include <cuda_fp16.h>
#include <mma.h>

using namespace nvcuda;

#define NN 100000
#define FF 128
#define HH 128
#define ZZ 64
#define EE 1600000
#define EPOS 200000
#define NCHUNK ((NN + 255) / 256)   // 391

// ---- scratch (static device globals) ----
__device__ __align__(16) int      g_cnt[NN];
__device__ __align__(16) int      g_bsum[512];
__device__ __align__(16) int      g_boff[512];
__device__ __align__(16) int      g_rowstart[NN + 1];
__device__ __align__(16) int      g_cursor[NN];
__device__ __align__(16) int      g_csr[EE];
__device__ __align__(16) float    g_dinv[NN];
__device__ __align__(16) unsigned g_hs1h[NN * 64];   // (x@W1)*dinv as half2 (128 cols)
__device__ __align__(16) unsigned g_hh[NN * 64];     // relu output as half2 (128 cols)
__device__ __align__(16) unsigned g_hs2h[NN * 32];   // (h@W2)*dinv as half2 (64 cols)
__device__ __align__(16) unsigned g_lath[NN * 32];   // latent as half2 (64 cols)

// ---------------- histogram / dinv ----------------
__global__ void cnt_count_k(const int* __restrict__ ei) {
    int t = blockIdx.x * blockDim.x + threadIdx.x;
    if (t < EE / 4) {
        int4 d = ((const int4*)(ei + EE))[t];
        atomicAdd(&g_cnt[d.x], 1);
        atomicAdd(&g_cnt[d.y], 1);
        atomicAdd(&g_cnt[d.z], 1);
        atomicAdd(&g_cnt[d.w], 1);
    }
}

__global__ void dinv_k() {
    int i = blockIdx.x * blockDim.x + threadIdx.x;
    if (i < NN) g_dinv[i] = rsqrtf((float)(g_cnt[i] + 1));
}

// ---------------- scan (3 small kernels) ----------------
__global__ void scan_bsum_k() {
    __shared__ int sh[256];
    int i = blockIdx.x * 256 + threadIdx.x;
    sh[threadIdx.x] = (i < NN) ? g_cnt[i] : 0;
    __syncthreads();
    for (int o = 128; o > 0; o >>= 1) {
        if (threadIdx.x < o) sh[threadIdx.x] += sh[threadIdx.x + o];
        __syncthreads();
    }
    if (threadIdx.x == 0) g_bsum[blockIdx.x] = sh[0];
}

__global__ void scan_boff_k() {
    __shared__ int sh[512];
    int t = threadIdx.x;
    int v = (t < NCHUNK) ? g_bsum[t] : 0;
    sh[t] = v;
    __syncthreads();
    for (int o = 1; o < 512; o <<= 1) {
        int add = (t >= o) ? sh[t - o] : 0;
        __syncthreads();
        sh[t] += add;
        __syncthreads();
    }
    g_boff[t] = sh[t] - v;
}

__global__ void scan_final_k() {
    __shared__ int sh[256];
    int t = threadIdx.x;
    int i = blockIdx.x * 256 + t;
    int v = (i < NN) ? g_cnt[i] : 0;
    sh[t] = v;
    __syncthreads();
    for (int o = 1; o < 256; o <<= 1) {
        int add = (t >= o) ? sh[t - o] : 0;
        __syncthreads();
        sh[t] += add;
        __syncthreads();
    }
    if (i < NN) {
        int rs = g_boff[blockIdx.x] + sh[t] - v;
        g_rowstart[i] = rs;
        g_cursor[i] = rs;
        if (i == NN - 1) g_rowstart[NN] = EE;
    }
}

__global__ void csr_fill_k(const int* __restrict__ ei) {
    int t = blockIdx.x * blockDim.x + threadIdx.x;
    if (t < EE / 4) {
        int4 s = ((const int4*)ei)[t];
        int4 d = ((const int4*)(ei + EE))[t];
        int p0 = atomicAdd(&g_cursor[d.x], 1); g_csr[p0] = s.x;
        int p1 = atomicAdd(&g_cursor[d.y], 1); g_csr[p1] = s.y;
        int p2 = atomicAdd(&g_cursor[d.z], 1); g_csr[p2] = s.z;
        int p3 = atomicAdd(&g_cursor[d.w], 1); g_csr[p3] = s.w;
    }
}

// ---------------- wmma GEMM: out = half2( (X @ W) * dinv[row] ) ----------------
// K fixed at 128. Block = 64 rows x NC cols, 256 threads = 8 warps.
template <int NC, bool XHALF>
__device__ __forceinline__ void wgemm_body(const void* __restrict__ Xv,
                                           const float* __restrict__ W,
                                           unsigned* __restrict__ outh) {
    constexpr int XS = 136;
    constexpr int WS = NC + 8;
    constexpr int CS = NC + 4;
    constexpr int NH = NC / 2;
    constexpr int NT = NC / 32;
    constexpr int SM_A = 64 * XS * 2;
    constexpr int SM_AB = SM_A + 64 * WS * 2;
    constexpr int SM_EPI = 64 * CS * 4;
    constexpr int SM_TOT = (SM_AB > SM_EPI) ? SM_AB : SM_EPI;
    __shared__ __align__(16) char sm[SM_TOT];
    half* Xh = (half*)sm;
    half* Wh = (half*)(sm + SM_A);
    float* Cs = (float*)sm;

    const int tid = threadIdx.x;
    const int row0 = blockIdx.x * 64;
    const int wid = tid >> 5;
    const int rw = wid >> 1;
    const int cw = wid & 1;

    if (XHALF) {
        const unsigned* Xs = (const unsigned*)Xv;
        for (int idx = tid; idx < 64 * 64; idx += 256) {
            int r = idx >> 6, c2 = idx & 63;
            int gr = row0 + r;
            unsigned v = (gr < NN) ? Xs[(long)gr * 64 + c2] : 0u;
            *(unsigned*)&Xh[r * XS + 2 * c2] = v;
        }
    } else {
        const float* Xf = (const float*)Xv;
        for (int idx = tid; idx < 64 * 64; idx += 256) {
            int r = idx >> 6, c2 = idx & 63;
            int gr = row0 + r;
            float2 v = (gr < NN) ? *(const float2*)&Xf[(long)gr * 128 + 2 * c2]
                                 : make_float2(0.f, 0.f);
            __half2 h = __float22half2_rn(v);
            *(unsigned*)&Xh[r * XS + 2 * c2] = *(unsigned*)&h;
        }
    }

    wmma::fragment<wmma::accumulator, 16, 16, 16, float> acc[NT];
#pragma unroll
    for (int t = 0; t < NT; t++) wmma::fill_fragment(acc[t], 0.0f);

    for (int kb = 0; kb < 128; kb += 64) {
        for (int idx = tid; idx < 64 * NH; idx += 256) {
            int kr = idx / NH, c2 = idx % NH;
            float2 v = *(const float2*)&W[(long)(kb + kr) * NC + 2 * c2];
            __half2 h = __float22half2_rn(v);
            *(unsigned*)&Wh[kr * WS + 2 * c2] = *(unsigned*)&h;
        }
        __syncthreads();
#pragma unroll
        for (int k0 = 0; k0 < 64; k0 += 16) {
            wmma::fragment<wmma::matrix_a, 16, 16, 16, half, wmma::row_major> af;
            wmma::load_matrix_sync(af, &Xh[(rw * 16) * XS + kb + k0], XS);
#pragma unroll
            for (int t = 0; t < NT; t++) {
                wmma::fragment<wmma::matrix_b, 16, 16, 16, half, wmma::row_major> bf;
                wmma::load_matrix_sync(bf, &Wh[k0 * WS + cw * NH + t * 16], WS);
                wmma::mma_sync(acc[t], af, bf, acc[t]);
            }
        }
        __syncthreads();
    }

#pragma unroll
    for (int t = 0; t < NT; t++)
        wmma::store_matrix_sync(&Cs[(rw * 16) * CS + cw * NH + t * 16], acc[t],
                                CS, wmma::mem_row_major);
    __syncthreads();
    for (int idx = tid; idx < 64 * NH; idx += 256) {
        int r = idx / NH, c2 = idx % NH;
        int gr = row0 + r;
        if (gr < NN) {
            float s = g_dinv[gr];
            float2 v = make_float2(Cs[r * CS + 2 * c2] * s,
                                   Cs[r * CS + 2 * c2 + 1] * s);
            __half2 h = __float22half2_rn(v);
            outh[(long)gr * NH + c2] = *(unsigned*)&h;
        }
    }
}

__global__ void __launch_bounds__(256) gemm1_k(const float* __restrict__ x,
                                               const float* __restrict__ W1) {
    wgemm_body<HH, false>(x, W1, g_hs1h);
}
__global__ void __launch_bounds__(256) gemm2_k(const float* __restrict__ W2) {
    wgemm_body<ZZ, true>(g_hh, W2, g_hs2h);
}

// ---------------- gather1: fp16 rows (128 cols), fp32 accumulation ----------------
__device__ __forceinline__ void h2acc4(float4& acc, uint2 v) {
    float2 lo = __half22float2(*(__half2*)&v.x);
    float2 hi = __half22float2(*(__half2*)&v.y);
    acc.x += lo.x; acc.y += lo.y; acc.z += hi.x; acc.w += hi.y;
}

__global__ void gather1_k(const float* __restrict__ b1) {
    int gt = blockIdx.x * blockDim.x + threadIdx.x;
    int n = gt >> 5;
    int lane = gt & 31;
    if (n >= NN) return;
    int s = g_rowstart[n];
    int e = g_rowstart[n + 1];

    float4 acc = make_float4(0.f, 0.f, 0.f, 0.f);
    h2acc4(acc, *(const uint2*)&g_hs1h[(long)n * 64 + lane * 2]);  // self-loop

    for (int base = s; base < e; base += 32) {
        int idx = base + lane;
        int myi = (idx < e) ? g_csr[idx] : 0;
        int cnt = min(32, e - base);
        int j = 0;
        for (; j + 8 <= cnt; j += 8) {
            int ss[8];
#pragma unroll
            for (int q = 0; q < 8; q++) ss[q] = __shfl_sync(0xffffffffu, myi, j + q);
            uint2 vv[8];
#pragma unroll
            for (int q = 0; q < 8; q++)
                vv[q] = *(const uint2*)&g_hs1h[(long)ss[q] * 64 + lane * 2];
#pragma unroll
            for (int q = 0; q < 8; q++) h2acc4(acc, vv[q]);
        }
        for (; j < cnt; j++) {
            int s0 = __shfl_sync(0xffffffffu, myi, j);
            h2acc4(acc, *(const uint2*)&g_hs1h[(long)s0 * 64 + lane * 2]);
        }
    }
    float d = g_dinv[n];
    float4 bb = *(const float4*)&b1[lane * 4];
    float4 o;
    o.x = fmaxf(fmaf(d, acc.x, bb.x), 0.0f);
    o.y = fmaxf(fmaf(d, acc.y, bb.y), 0.0f);
    o.z = fmaxf(fmaf(d, acc.z, bb.z), 0.0f);
    o.w = fmaxf(fmaf(d, acc.w, bb.w), 0.0f);
    __half2 h0 = __float22half2_rn(make_float2(o.x, o.y));
    __half2 h1 = __float22half2_rn(make_float2(o.z, o.w));
    *(uint2*)&g_hh[(long)n * 64 + lane * 2] =
        make_uint2(*(unsigned*)&h0, *(unsigned*)&h1);
}

// ---------------- gather2: fp16 rows (64 cols), fp32 accumulation ----------------
__global__ void gather2_k(const float* __restrict__ b2) {
    int gt = blockIdx.x * blockDim.x + threadIdx.x;
    int n = gt >> 5;
    int lane = gt & 31;
    if (n >= NN) return;
    int s = g_rowstart[n];
    int e = g_rowstart[n + 1];

    float2 acc;
    {
        unsigned v = g_hs2h[(long)n * 32 + lane];  // self-loop (scaled)
        acc = __half22float2(*(__half2*)&v);
    }

    for (int base = s; base < e; base += 32) {
        int idx = base + lane;
        int myi = (idx < e) ? g_csr[idx] : 0;
        int cnt = min(32, e - base);
        int j = 0;
        for (; j + 8 <= cnt; j += 8) {
            int ss[8];
#pragma unroll
            for (int q = 0; q < 8; q++) ss[q] = __shfl_sync(0xffffffffu, myi, j + q);
            unsigned vv[8];
#pragma unroll
            for (int q = 0; q < 8; q++)
                vv[q] = g_hs2h[(long)ss[q] * 32 + lane];
#pragma unroll
            for (int q = 0; q < 8; q++) {
                float2 f = __half22float2(*(__half2*)&vv[q]);
                acc.x += f.x; acc.y += f.y;
            }
        }
        for (; j < cnt; j++) {
            int s0 = __shfl_sync(0xffffffffu, myi, j);
            unsigned v = g_hs2h[(long)s0 * 32 + lane];
            float2 f = __half22float2(*(__half2*)&v);
            acc.x += f.x; acc.y += f.y;
        }
    }
    float d = g_dinv[n];
    float2 bb = *(const float2*)&b2[lane * 2];
    float2 o;
    o.x = fmaf(d, acc.x, bb.x);
    o.y = fmaf(d, acc.y, bb.y);
    __half2 hv = __float22half2_rn(o);
    g_lath[(long)n * 32 + lane] = *(unsigned*)&hv;
}

// ---------------- decoder: fp16 latent ----------------
__global__ void decode_k(const int* __restrict__ pe,
                         const int* __restrict__ ne,
                         float* __restrict__ out) {
    int gt = blockIdx.x * blockDim.x + threadIdx.x;
    int w = gt >> 5;
    int lane = gt & 31;
    if (w >= 2 * EPOS) return;
    int a, b;
    if (w < EPOS) {
        a = pe[w];
        b = pe[EPOS + w];
    } else {
        int k = w - EPOS;
        a = ne[k];
        b = ne[EPOS + k];
    }
    unsigned ua = g_lath[(long)a * 32 + lane];
    unsigned ub = g_lath[(long)b * 32 + lane];
    float2 u = __half22float2(*(__half2*)&ua);
    float2 v = __half22float2(*(__half2*)&ub);
    float s = u.x * v.x + u.y * v.y;
#pragma unroll
    for (int o = 16; o > 0; o >>= 1) s += __shfl_xor_sync(0xffffffffu, s, o);
    if (lane == 0) out[w] = s;
}

// ---------------- launch (R14 structure; memset init; int4 edge kernels) ----------------
extern "C" void kernel_launch(void* const* d_in, const int* in_sizes, int n_in,
                              void* d_out, int out_size) {
    const float* x = (const float*)d_in[0];
    const float* W1 = (const float*)d_in[1];
    const float* b1 = (const float*)d_in[2];
    const float* W2 = (const float*)d_in[3];
    const float* b2 = (const float*)d_in[4];
    const int* ei = (const int*)d_in[5];
    const int* pe = (const int*)d_in[6];
    const int* ne = (const int*)d_in[7];
    float* out = (float*)d_out;

    static cudaStream_t sB = nullptr;
    static cudaEvent_t evF = nullptr, evJ = nullptr;
    static void* cntPtr = nullptr;
    if (sB == nullptr) {
        cudaStreamCreateWithFlags(&sB, cudaStreamNonBlocking);
        cudaEventCreateWithFlags(&evF, cudaEventDisableTiming);
        cudaEventCreateWithFlags(&evJ, cudaEventDisableTiming);
        cudaGetSymbolAddress(&cntPtr, g_cnt);
    }

    // serial prefix: degree histogram (both branches need it)
    cudaMemsetAsync(cntPtr, 0, NN * sizeof(int), 0);
    cnt_count_k<<<(EE / 4 + 255) / 256, 256>>>(ei);

    // fork: scan+fill on sB; dinv+gemm1 on stream 0
    cudaEventRecord(evF, 0);
    cudaStreamWaitEvent(sB, evF, 0);
    scan_bsum_k<<<NCHUNK, 256, 0, sB>>>();
    scan_boff_k<<<1, 512, 0, sB>>>();
    scan_final_k<<<NCHUNK, 256, 0, sB>>>();
    csr_fill_k<<<(EE / 4 + 255) / 256, 256, 0, sB>>>(ei);
    cudaEventRecord(evJ, sB);

    dinv_k<<<(NN + 255) / 256, 256>>>();
    gemm1_k<<<(NN + 63) / 64, 256>>>(x, W1);

    // join: gather1 needs csr + gemm1
    cudaStreamWaitEvent(0, evJ, 0);

    gather1_k<<<(NN * 32 + 255) / 256, 256>>>(b1);
    gemm2_k<<<(NN + 63) / 64, 256>>>(W2);
    gather2_k<<<(NN * 32 + 255) / 256, 256>>>(b2);
    decode_k<<<(2 * EPOS * 32 + 255) / 256, 256>>>(pe, ne, out);
}